// round 5
// baseline (speedup 1.0000x reference)
#include <cuda_runtime.h>
#include <cuda_fp16.h>
#include <cstddef>

// ForwardSim via mma.sync HMMA (sm_103 baseline; tcgen05 is 'a'-gated).
// R5: 128 rows/CTA, 8 warps = 4 mb x 2 ch; each warp owns 32 rows x 64 cols so
// every B-fragment and W1e load is amortized over 2 m-blocks. PACC stored
// fragment-native (conflict-free coalesced LDS.128). 3-term fp16 split GEMM.

using u32 = unsigned int;
using u64 = unsigned long long;

namespace {
constexpr int kB = 32768, kT = 50, kH = 128, kM = 128, kThreads = 256;

constexpr int OFF_BFRAG = 0;        // 65536: W2 frags (c2,kb,nf,lane) 16B
constexpr int OFF_PACC  = 65536;    // 65536: projAcc frags (mb,kb,i,g,q) 16B
constexpr int OFF_W1EP  = 131072;   // 4608:  W1 rows 64..72, perm cols
constexpr int OFF_ENV   = 135680;   // 6656:  128 x 13 f32
constexpr int OFF_BW    = 142336;   // 1024:  (b2 pair, W3 pair) per 2 cols
constexpr int OFF_PART  = 143360;   // 1024:  2 x 128 partials / b1p alias
constexpr int OFF_SC    = 144384;   // 64
constexpr int SMEM_BYTES = 144448;
constexpr int OFF_W1P   = 0;        // phase alias inside BFRAG: 64x128 f32
} // namespace

__device__ __forceinline__ u64 pack_dup(float v) {
    u64 r; asm("mov.b64 %0, {%1, %1};" : "=l"(r) : "f"(v)); return r;
}
__device__ __forceinline__ void unpack2(u64 v, float& a, float& b) {
    asm("mov.b64 {%0, %1}, %2;" : "=f"(a), "=f"(b) : "l"(v));
}
__device__ __forceinline__ u64 fma2(u64 a, u64 b, u64 c) {
    u64 d; asm("fma.rn.f32x2 %0, %1, %2, %3;" : "=l"(d) : "l"(a), "l"(b), "l"(c));
    return d;
}
// col permutation: orig col c -> index so thread q's mma cols {2q,2q+1,2q+8,2q+9}
// per 16-block are contiguous at q*4..q*4+3
__device__ __forceinline__ int pcol(int c) {
    return (c & ~15) | (((c >> 1) & 3) << 2) | (((c >> 3) & 1) << 1) | (c & 1);
}
__device__ __forceinline__ void split2(float f0, float f1, u32& hi, u32& lo) {
    __half h0 = __float2half_rn(f0), h1 = __float2half_rn(f1);
    __half2 hh = __halves2half2(h0, h1);
    hi = reinterpret_cast<u32&>(hh);
    __half2 ll = __floats2half2_rn(f0 - __half2float(h0),
                                   f1 - __half2float(h1));
    lo = reinterpret_cast<u32&>(ll);
}
__device__ __forceinline__ void relu_split(u64 h, u32& hi, u32& lo) {
    float f0, f1;
    unpack2(h, f0, f1);
    split2(fmaxf(f0, 0.f), fmaxf(f1, 0.f), hi, lo);
}
__device__ __forceinline__ void mma16816(float d[4], u32 a0, u32 a1, u32 a2,
                                         u32 a3, u32 b0, u32 b1) {
    asm volatile(
        "mma.sync.aligned.m16n8k16.row.col.f32.f16.f16.f32 "
        "{%0,%1,%2,%3}, {%4,%5,%6,%7}, {%8,%9}, {%0,%1,%2,%3};"
        : "+f"(d[0]), "+f"(d[1]), "+f"(d[2]), "+f"(d[3])
        : "r"(a0), "r"(a1), "r"(a2), "r"(a3), "r"(b0), "r"(b1));
}

__global__ void __launch_bounds__(kThreads, 1)
fsim_mma(const float* __restrict__ proj, const float* __restrict__ idm,
         const float* __restrict__ merg, const float* __restrict__ W1,
         const float* __restrict__ b1,   const float* __restrict__ W2,
         const float* __restrict__ b2,   const float* __restrict__ W3,
         const float* __restrict__ b3,   const float* __restrict__ smean,
         const float* __restrict__ svar, float* __restrict__ out)
{
    extern __shared__ char smem[];
    float* smf = (float*)smem;

    const int tid = threadIdx.x, wid = tid >> 5, lane = tid & 31;
    const int mb = wid >> 1, ch = wid & 1, g = lane >> 2, q = lane & 3;
    const int rowBase = blockIdx.x * kM;

    // ---------------- phase A: stage ----------------
    for (int i = tid; i < 64 * kH; i += kThreads) {
        int k = i >> 7, c = i & 127;
        smf[(OFF_W1P >> 2) + k * 128 + pcol(c)] = W1[i];
    }
    for (int i = tid; i < 9 * kH; i += kThreads) {
        int j = i >> 7, c = i & 127;
        smf[(OFF_W1EP >> 2) + j * 128 + pcol(c)] = W1[64 * kH + i];
    }
    if (tid < 128)  // permuted b1 (PART alias, consumed by phase B)
        smf[(OFF_PART >> 2) + pcol(tid)] = b1[tid];
    if (tid < 64) {
        int c = tid * 2;
        float4 v;
        v.x = b2[c]; v.y = b2[c + 1]; v.z = W3[c]; v.w = W3[c + 1];
        *(float4*)(smem + OFF_BW + tid * 16) = v;
    }
    if (tid < 6) {
        smf[(OFF_SC >> 2) + tid]     = smean[tid];
        smf[(OFF_SC >> 2) + 8 + tid] = rsqrtf(svar[tid]);
    }
    __syncthreads();

    // -------- phase B: projAcc = proj@W1[:64] + b1 -> fragment-native smem --
    for (int task = tid; task < 1024; task += kThreads) {
        int r = task >> 3, cg = task & 7;   // row, k-block (perm col group)
        const float* prow = proj + (size_t)(rowBase + r) * 64;
        u64 acc[8];
        const u64* bp = (const u64*)&smf[(OFF_PART >> 2) + cg * 16];
        #pragma unroll
        for (int e = 0; e < 8; e++) acc[e] = bp[e];
        #pragma unroll 4
        for (int k4 = 0; k4 < 16; k4++) {
            float4 av = __ldg((const float4*)(prow + k4 * 4));
            float avv[4] = {av.x, av.y, av.z, av.w};
            #pragma unroll
            for (int e2 = 0; e2 < 4; e2++) {
                u64 a = pack_dup(avv[e2]);
                const u64* w = (const u64*)
                    &smf[(OFF_W1P >> 2) + (k4 * 4 + e2) * 128 + cg * 16];
                #pragma unroll
                for (int e = 0; e < 8; e++) acc[e] = fma2(a, w[e], acc[e]);
            }
        }
        int mbb = r >> 5, rem = r & 31, gg = rem & 7, ii = rem >> 3;
        char* base = smem + OFF_PACC +
                     (size_t)((((mbb * 8 + cg) * 4 + ii) * 8 + gg) * 4) * 16;
        #pragma unroll
        for (int qq = 0; qq < 4; qq++)
            *(ulonglong2*)(base + qq * 16) =
                make_ulonglong2(acc[2 * qq], acc[2 * qq + 1]);
    }
    __syncthreads();

    // -------- phase C: W2 -> fragment-native fp16 hi/lo (overwrites W1P) ---
    for (int i = tid; i < 4096; i += kThreads) {
        int t  = i & 31, nf = (i >> 5) & 7, kb = (i >> 8) & 7, c2 = (i >> 11) & 1;
        int gg = t >> 2, qq = t & 3;
        int n  = c2 * 64 + nf * 8 + gg;
        int k0 = kb * 16 + qq * 2;
        float w00 = W2[(size_t)k0 * 128 + n];
        float w01 = W2[(size_t)(k0 + 1) * 128 + n];
        float w10 = W2[(size_t)(k0 + 8) * 128 + n];
        float w11 = W2[(size_t)(k0 + 9) * 128 + n];
        u32 h0, l0, h1v, l1v;
        split2(w00, w01, h0, l0);
        split2(w10, w11, h1v, l1v);
        ulonglong2 e;
        e.x = ((u64)h1v << 32) | h0;
        e.y = ((u64)l1v << 32) | l0;
        *(ulonglong2*)(smem + OFF_BFRAG +
                       (size_t)(((c2 * 8 + kb) * 8 + nf) * 32 + t) * 16) = e;
    }
    __syncthreads();

    const float b3v = __ldg(&b3[0]);
    float ego_v = 0.f, ego_x = 0.f, act_c = 0.f;   // carry lives in tid<128

    // ================= timestep loop =================
    for (int t = 0; t < kT; t++) {
        // ---- env features (one thread per row) ----
        if (tid < kM) {
            const float* sp = idm + (size_t)(rowBase + tid) * (kT * 12) + t * 12;
            float4 a0 = *(const float4*)sp;
            float4 a1 = *(const float4*)(sp + 4);
            float s11 = sp[11];
            if (t == 0) { ego_v = a0.x; ego_x = a0.w; }
            else {
                ego_v = fmaf(act_c, 0.1f, ego_v);
                ego_x = ego_x + ego_v * 0.1f + act_c * 0.005f;
            }
            float ev[6];
            ev[0] = ego_v;
            ev[1] = a0.y;
            ev[2] = ego_v - a0.y;
            ev[3] = a1.x - ego_x;
            ev[4] = (ego_v - a0.z) * s11;
            ev[5] = (a1.y - ego_x) * s11 + (1.0f - s11) * 100.0f;
            #pragma unroll
            for (int j = 0; j < 6; j++)
                smf[(OFF_ENV >> 2) + tid * 13 + j] =
                    (ev[j] - smf[(OFF_SC >> 2) + j]) * smf[(OFF_SC >> 2) + 8 + j];
            const float* mp = merg + (size_t)(rowBase + tid) * (kT * 3) + t * 3;
            smf[(OFF_ENV >> 2) + tid * 13 + 6] = mp[0];
            smf[(OFF_ENV >> 2) + tid * 13 + 7] = mp[1];
            smf[(OFF_ENV >> 2) + tid * 13 + 8] = mp[2];
        }
        __syncthreads();

        // env for this thread's 4 fragment rows (mb*32 + g + 8i)
        float e[4][9];
        #pragma unroll
        for (int i = 0; i < 4; i++) {
            int rr = mb * 32 + g + 8 * i;
            #pragma unroll
            for (int j = 0; j < 9; j++)
                e[i][j] = smf[(OFF_ENV >> 2) + rr * 13 + j];
        }

        float d[2][8][4];
        #pragma unroll
        for (int b = 0; b < 2; b++)
            #pragma unroll
            for (int nf = 0; nf < 8; nf++)
                d[b][nf][0] = d[b][nf][1] = d[b][nf][2] = d[b][nf][3] = 0.f;

        #pragma unroll
        for (int kb = 0; kb < 8; kb++) {
            // h1 fragments for 4 rows: projAcc (fragment-native) + env @ W1e
            const char* pb = smem + OFF_PACC +
                (size_t)((((mb * 8 + kb) * 4) * 8 + g) * 4 + q) * 16;
            u64 hx[4], hy[4];
            #pragma unroll
            for (int i = 0; i < 4; i++) {
                ulonglong2 p = *(const ulonglong2*)(pb + i * 512);
                hx[i] = p.x; hy[i] = p.y;
            }
            #pragma unroll
            for (int j = 0; j < 9; j++) {
                ulonglong2 w = *(const ulonglong2*)
                    (smem + OFF_W1EP + (size_t)(j * 128 + kb * 16 + q * 4) * 4);
                #pragma unroll
                for (int i = 0; i < 4; i++) {
                    u64 m = pack_dup(e[i][j]);
                    hx[i] = fma2(m, w.x, hx[i]);
                    hy[i] = fma2(m, w.y, hy[i]);
                }
            }
            u32 ax[4], lx[4], ay[4], ly[4];
            #pragma unroll
            for (int i = 0; i < 4; i++) {
                relu_split(hx[i], ax[i], lx[i]);
                relu_split(hy[i], ay[i], ly[i]);
            }
            const char* bfp = smem + OFF_BFRAG +
                              (size_t)((ch * 8 + kb) * 8) * 512 + lane * 16;
            #pragma unroll
            for (int nf = 0; nf < 8; nf++) {
                ulonglong2 bf = *(const ulonglong2*)(bfp + nf * 512);
                u32 bh0 = (u32)bf.x, bh1 = (u32)(bf.x >> 32);
                u32 bl0 = (u32)bf.y, bl1 = (u32)(bf.y >> 32);
                #pragma unroll
                for (int b = 0; b < 2; b++) {
                    mma16816(d[b][nf], ax[2*b], ax[2*b+1], ay[2*b], ay[2*b+1],
                             bh0, bh1);                                // hi*hi
                    mma16816(d[b][nf], lx[2*b], lx[2*b+1], ly[2*b], ly[2*b+1],
                             bh0, bh1);                                // lo*hi
                    mma16816(d[b][nf], ax[2*b], ax[2*b+1], ay[2*b], ay[2*b+1],
                             bl0, bl1);                                // hi*lo
                }
            }
        }

        // ---- epilogue: relu(D + b2) . W3 ----
        float s[4] = {0.f, 0.f, 0.f, 0.f};
        #pragma unroll
        for (int nf = 0; nf < 8; nf++) {
            float4 bw = *(const float4*)(smem + OFF_BW +
                                         (ch * 32 + nf * 4 + q) * 16);
            #pragma unroll
            for (int b = 0; b < 2; b++) {
                s[2*b]   += fmaxf(d[b][nf][0] + bw.x, 0.f) * bw.z +
                            fmaxf(d[b][nf][1] + bw.y, 0.f) * bw.w;
                s[2*b+1] += fmaxf(d[b][nf][2] + bw.x, 0.f) * bw.z +
                            fmaxf(d[b][nf][3] + bw.y, 0.f) * bw.w;
            }
        }
        #pragma unroll
        for (int i = 0; i < 4; i++) {
            s[i] += __shfl_xor_sync(0xFFFFFFFFu, s[i], 1);
            s[i] += __shfl_xor_sync(0xFFFFFFFFu, s[i], 2);
        }
        if (q == 0) {
            #pragma unroll
            for (int i = 0; i < 4; i++)
                smf[(OFF_PART >> 2) + ch * 128 + mb * 32 + g + 8 * i] = s[i];
        }
        __syncthreads();

        if (tid < kM) {
            float a = smf[(OFF_PART >> 2) + tid] +
                      smf[(OFF_PART >> 2) + 128 + tid] + b3v;
            act_c = a;
            out[(size_t)(rowBase + tid) * kT + t] = a;
        }
        // env(t+1) is written by the same tid<128 threads; all other warps
        // re-block at the next __syncthreads() before reading env.
    }
}

extern "C" void kernel_launch(void* const* d_in, const int* in_sizes, int n_in,
                              void* d_out, int out_size)
{
    (void)in_sizes; (void)n_in; (void)out_size;
    const float* proj  = (const float*)d_in[0];
    const float* idm   = (const float*)d_in[1];
    const float* merg  = (const float*)d_in[2];
    const float* W1    = (const float*)d_in[3];
    const float* b1    = (const float*)d_in[4];
    const float* W2    = (const float*)d_in[5];
    const float* b2    = (const float*)d_in[6];
    const float* W3    = (const float*)d_in[7];
    const float* b3    = (const float*)d_in[8];
    const float* smean = (const float*)d_in[9];
    const float* svar  = (const float*)d_in[10];
    float* out = (float*)d_out;

    cudaFuncSetAttribute(fsim_mma, cudaFuncAttributeMaxDynamicSharedMemorySize,
                         SMEM_BYTES);
    fsim_mma<<<kB / kM, kThreads, SMEM_BYTES>>>(
        proj, idm, merg, W1, b1, W2, b2, W3, b3, smean, svar, out);
}